// round 16
// baseline (speedup 1.0000x reference)
#include <cuda_runtime.h>
#include <cuda_fp16.h>
#include <cstdint>

#define NN 8192
#define DD 128
#define K2C 20.6099286f    // 1/(0.07*ln2)

#define NTILE 64
#define NPAIR 1056
#define SMEM_BYTES 98304

// ---------------------------------------------------------------------------
__device__ uint32_t g_h[NN * 64];    // normalized feats, fp16x2
__device__ float    g_rowsum[NN];
__device__ float    g_pos[NN];

__device__ __forceinline__ uint32_t smem_u32(const void* p) {
    uint32_t a;
    asm("{ .reg .u64 t; cvta.to.shared.u64 t, %1; cvt.u32.u64 %0, t; }" : "=r"(a) : "l"(p));
    return a;
}
__device__ __forceinline__ float ex2f(float x) {
    float y; asm("ex2.approx.ftz.f32 %0, %1;" : "=f"(y) : "f"(x)); return y;
}
__device__ __forceinline__ float lg2f(float x) {
    float y; asm("lg2.approx.f32 %0, %1;" : "=f"(y) : "f"(x)); return y;
}
__device__ __forceinline__ void cp16(uint32_t dst, const void* src) {
    asm volatile("cp.async.cg.shared.global [%0], [%1], 16;" :: "r"(dst), "l"(src));
}
#define CP_COMMIT() asm volatile("cp.async.commit_group;" ::: "memory")
#define CP_WAIT(n)  asm volatile("cp.async.wait_group %0;" :: "n"(n) : "memory")

#define LDSM4(r0, r1, r2, r3, a) \
    asm volatile("ldmatrix.sync.aligned.m8n8.x4.shared.b16 {%0,%1,%2,%3}, [%4];" \
                 : "=r"(r0), "=r"(r1), "=r"(r2), "=r"(r3) : "r"(a))
#define MMA16816(d, a, b0v, b1v) \
    asm volatile("mma.sync.aligned.m16n8k16.row.col.f32.f16.f16.f32 " \
                 "{%0,%1,%2,%3},{%4,%5,%6,%7},{%8,%9},{%0,%1,%2,%3};" \
                 : "+f"((d)[0]), "+f"((d)[1]), "+f"((d)[2]), "+f"((d)[3]) \
                 : "r"((a)[0]), "r"((a)[1]), "r"((a)[2]), "r"((a)[3]), \
                   "r"(b0v), "r"(b1v))

// ---------------------------------------------------------------------------
// Kernel 1: row L2-normalize -> fp16 (warp per row), zero rowsum
// ---------------------------------------------------------------------------
__global__ void norm_kernel(const float* __restrict__ feats) {
    int row  = blockIdx.x * 8 + (threadIdx.x >> 5);
    int lane = threadIdx.x & 31;
    float4 v = ((const float4*)(feats + (size_t)row * DD))[lane];
    float ss = v.x * v.x + v.y * v.y + v.z * v.z + v.w * v.w;
    #pragma unroll
    for (int o = 16; o; o >>= 1) ss += __shfl_xor_sync(0xffffffffu, ss, o);
    float inv = 1.0f / fmaxf(sqrtf(ss), 1e-8f);
    __half2 p0 = __floats2half2_rn(v.x * inv, v.y * inv);
    __half2 p1 = __floats2half2_rn(v.z * inv, v.w * inv);
    uint2 pk;
    pk.x = *(uint32_t*)&p0;
    pk.y = *(uint32_t*)&p1;
    *(uint2*)(g_h + (size_t)row * 64 + lane * 2) = pk;
    if (lane == 0) g_rowsum[row] = 0.0f;
}

// ---------------------------------------------------------------------------
// Kernel 2: triangular pair sweep, barrier-free (R15) + specialized epilogues
// ---------------------------------------------------------------------------
__device__ __forceinline__ void copy_tile_async(uint32_t smemBase,
                                                const uint4* __restrict__ src,
                                                int tid) {
    #pragma unroll
    for (int i = 0; i < 8; i++) {
        int idx = tid + i * 256;
        int r = idx >> 4, c = idx & 15;
        uint32_t dst = smemBase + (uint32_t)((r * 16 + (c ^ (r & 7))) << 4);
        cp16(dst, src + idx);
    }
}

__global__ void __launch_bounds__(256, 2) sim_kernel() {
    extern __shared__ uint4 sm4[];
    const int tid  = threadIdx.x;
    const int lane = tid & 31;
    const int wid  = tid >> 5;

    // decode bid -> (rt, pairIdx); pairs(rt) = 32 - (rt>>1)
    int rt = 0, cum = 0;
    {
        const int bid = blockIdx.x;
        while (cum + (32 - (rt >> 1)) <= bid) { cum += 32 - (rt >> 1); rt++; }
    }
    const int pairIdx = (int)blockIdx.x - cum;
    const int ct0  = rt + 2 * pairIdx;
    const int numT = (ct0 + 1 < NTILE) ? 2 : 1;
    const int rowBase = rt * 128;

    const uint32_t smA  = smem_u32(sm4);
    const uint32_t smB0 = smA + 32768;
    const uint32_t smB1 = smA + 65536;

    // prologue: load A, B0, B1; single wait + barrier; barrier-free after
    copy_tile_async(smA, (const uint4*)g_h + (size_t)rowBase * 16, tid);
    if (ct0 != rt)
        copy_tile_async(smB0, (const uint4*)g_h + (size_t)(ct0 * 128) * 16, tid);
    if (numT == 2)
        copy_tile_async(smB1, (const uint4*)g_h + (size_t)((ct0 + 1) * 128) * 16, tid);
    CP_COMMIT();
    CP_WAIT(0);
    __syncthreads();

    const int warpM = wid & 1;
    const int warpN = wid >> 1;
    const int aRowL = warpM * 64 + (lane & 15);
    const int aCB   = lane >> 4;
    const int bRowL = warpN * 32 + ((lane & 7) | ((lane >> 1) & 8));
    const int bCB   = (lane >> 3) & 1;

    const int rBase0 = rowBase + warpM * 64 + (lane >> 2);
    const int cOffW  = warpN * 32 + (lane & 3) * 2;

    float racc[4][2];
    #pragma unroll
    for (int u = 0; u < 4; u++) { racc[u][0] = 0.0f; racc[u][1] = 0.0f; }

    for (int t = 0; t < numT; t++) {
        const int ct = ct0 + t;
        const int colBase = ct * 128;
        const bool isDiag = (ct == rt);
        const bool hasPos = (ct == rt + 32);
        const uint32_t smB = isDiag ? smA : (t == 0 ? smB0 : smB1);

        float C[4][4][4];
        #pragma unroll
        for (int mi = 0; mi < 4; mi++)
            #pragma unroll
            for (int nj = 0; nj < 4; nj++)
                #pragma unroll
                for (int q = 0; q < 4; q++) C[mi][nj][q] = 0.0f;

        #pragma unroll
        for (int ks = 0; ks < 8; ks++) {
            uint32_t a[4][4], b[2][4];
            #pragma unroll
            for (int mi = 0; mi < 4; mi++) {
                int r = aRowL + mi * 16;
                int ch = 2 * ks + aCB;
                LDSM4(a[mi][0], a[mi][1], a[mi][2], a[mi][3],
                      smA + r * 256 + ((ch ^ (r & 7)) << 4));
            }
            #pragma unroll
            for (int nh = 0; nh < 2; nh++) {
                int r = bRowL + nh * 16;
                int ch = 2 * ks + bCB;
                LDSM4(b[nh][0], b[nh][1], b[nh][2], b[nh][3],
                      smB + r * 256 + ((ch ^ (r & 7)) << 4));
            }
            #pragma unroll
            for (int mi = 0; mi < 4; mi++)
                #pragma unroll
                for (int nj = 0; nj < 4; nj++)
                    MMA16816(C[mi][nj], a[mi], b[nj >> 1][(nj & 1) * 2],
                             b[nj >> 1][(nj & 1) * 2 + 1]);
        }

        // ---- specialized epilogues (no barriers) ----
        const int cBase0 = colBase + cOffW;
        if (isDiag) {
            // 64 tiles: row-only, diag-skip compare required
            #pragma unroll
            for (int mi = 0; mi < 4; mi++)
                #pragma unroll
                for (int h = 0; h < 2; h++) {
                    const int grow = rBase0 + mi * 16 + h * 8;
                    float acc = 0.0f;
                    #pragma unroll
                    for (int nj = 0; nj < 4; nj++)
                        #pragma unroll
                        for (int q = 0; q < 2; q++) {
                            const int gcol = cBase0 + nj * 8 + q;
                            const float s = C[mi][nj][h * 2 + q];
                            if (gcol != grow) acc += ex2f(fmaf(s, K2C, -K2C));
                        }
                    racc[mi][h] += acc;
                }
        } else {
            float cacc[4][2];
            #pragma unroll
            for (int u = 0; u < 4; u++) { cacc[u][0] = 0.0f; cacc[u][1] = 0.0f; }

            if (hasPos) {
                // 32 tiles: dual-acc + per-element pos capture
                #pragma unroll
                for (int mi = 0; mi < 4; mi++)
                    #pragma unroll
                    for (int h = 0; h < 2; h++) {
                        const int grow = rBase0 + mi * 16 + h * 8;
                        const int pcol = grow ^ (NN / 2);
                        float acc = 0.0f;
                        #pragma unroll
                        for (int nj = 0; nj < 4; nj++)
                            #pragma unroll
                            for (int q = 0; q < 2; q++) {
                                const int gcol = cBase0 + nj * 8 + q;
                                const float s = C[mi][nj][h * 2 + q];
                                const float e = ex2f(fmaf(s, K2C, -K2C));
                                acc += e;
                                cacc[nj][q] += e;
                                if (gcol == pcol) {
                                    g_pos[grow] = s;
                                    g_pos[gcol] = s;
                                }
                            }
                        racc[mi][h] += acc;
                    }
            } else {
                // 1984 tiles: CLEAN — zero per-element compares
                #pragma unroll
                for (int mi = 0; mi < 4; mi++)
                    #pragma unroll
                    for (int h = 0; h < 2; h++) {
                        float acc = 0.0f;
                        #pragma unroll
                        for (int nj = 0; nj < 4; nj++)
                            #pragma unroll
                            for (int q = 0; q < 2; q++) {
                                const float e =
                                    ex2f(fmaf(C[mi][nj][h * 2 + q], K2C, -K2C));
                                acc += e;
                                cacc[nj][q] += e;
                            }
                        racc[mi][h] += acc;
                    }
            }

            #pragma unroll
            for (int nj = 0; nj < 4; nj++)
                #pragma unroll
                for (int q = 0; q < 2; q++) {
                    float v = cacc[nj][q];
                    v += __shfl_xor_sync(0xffffffffu, v, 4);
                    v += __shfl_xor_sync(0xffffffffu, v, 8);
                    v += __shfl_xor_sync(0xffffffffu, v, 16);
                    if (lane < 4)
                        atomicAdd(&g_rowsum[cBase0 + nj * 8 + q], v);
                }
        }
    }

    // row reduction once for both tiles
    #pragma unroll
    for (int mi = 0; mi < 4; mi++)
        #pragma unroll
        for (int h = 0; h < 2; h++) {
            float v = racc[mi][h];
            v += __shfl_xor_sync(0xffffffffu, v, 1);
            v += __shfl_xor_sync(0xffffffffu, v, 2);
            if ((lane & 3) == 0)
                atomicAdd(&g_rowsum[rBase0 + mi * 16 + h * 8], v);
        }
}

// ---------------------------------------------------------------------------
// Kernel 3: loss = mean( (1 - pos)/T + ln(rowsum) )
// ---------------------------------------------------------------------------
__global__ void finish_kernel(float* __restrict__ out) {
    __shared__ float red[1024];
    const int tid = threadIdx.x;
    float acc = 0.0f;
    for (int r = tid; r < NN; r += 1024)
        acc += (1.0f - g_pos[r]) * (1.0f / 0.07f) + lg2f(g_rowsum[r]) * 0.69314718f;
    red[tid] = acc;
    __syncthreads();
    #pragma unroll
    for (int s = 512; s > 0; s >>= 1) {
        if (tid < s) red[tid] += red[tid + s];
        __syncthreads();
    }
    if (tid == 0) out[0] = red[0] / (float)NN;
}

// ---------------------------------------------------------------------------
extern "C" void kernel_launch(void* const* d_in, const int* in_sizes, int n_in,
                              void* d_out, int out_size) {
    const float* feats = (const float*)d_in[0];
    float* out = (float*)d_out;

    cudaFuncSetAttribute(sim_kernel, cudaFuncAttributeMaxDynamicSharedMemorySize,
                         SMEM_BYTES);

    norm_kernel<<<NN / 8, 256>>>(feats);
    sim_kernel<<<NPAIR, 256, SMEM_BYTES>>>();
    finish_kernel<<<1, 1024>>>(out);
}

// round 17
// speedup vs baseline: 1.0604x; 1.0604x over previous
#include <cuda_runtime.h>
#include <cuda_fp16.h>
#include <cstdint>

#define NN 8192
#define DD 128
#define K2C 20.6099286f          // 1/(0.07*ln2)
#define SSH 12.0f                // exponent shift (rowsum scaled by 2^12)
#define CSH (SSH - K2C)          // arg = s*K2C + CSH

#define NTILE 64
#define NPAIR 1056
#define SMEM_BYTES 98304

// ---------------------------------------------------------------------------
__device__ uint32_t g_h[NN * 64];    // normalized feats, fp16x2
__device__ float    g_rowsum[NN];    // scaled by 2^SSH
__device__ float    g_pos[NN];

__device__ __forceinline__ uint32_t smem_u32(const void* p) {
    uint32_t a;
    asm("{ .reg .u64 t; cvta.to.shared.u64 t, %1; cvt.u32.u64 %0, t; }" : "=r"(a) : "l"(p));
    return a;
}
__device__ __forceinline__ float ex2f(float x) {
    float y; asm("ex2.approx.ftz.f32 %0, %1;" : "=f"(y) : "f"(x)); return y;
}
__device__ __forceinline__ float lg2f(float x) {
    float y; asm("lg2.approx.f32 %0, %1;" : "=f"(y) : "f"(x)); return y;
}
__device__ __forceinline__ void cp16(uint32_t dst, const void* src) {
    asm volatile("cp.async.cg.shared.global [%0], [%1], 16;" :: "r"(dst), "l"(src));
}
#define CP_COMMIT() asm volatile("cp.async.commit_group;" ::: "memory")
#define CP_WAIT(n)  asm volatile("cp.async.wait_group %0;" :: "n"(n) : "memory")

#define LDSM4(r0, r1, r2, r3, a) \
    asm volatile("ldmatrix.sync.aligned.m8n8.x4.shared.b16 {%0,%1,%2,%3}, [%4];" \
                 : "=r"(r0), "=r"(r1), "=r"(r2), "=r"(r3) : "r"(a))
#define MMA16816(d, a, b0v, b1v) \
    asm volatile("mma.sync.aligned.m16n8k16.row.col.f32.f16.f16.f32 " \
                 "{%0,%1,%2,%3},{%4,%5,%6,%7},{%8,%9},{%0,%1,%2,%3};" \
                 : "+f"((d)[0]), "+f"((d)[1]), "+f"((d)[2]), "+f"((d)[3]) \
                 : "r"((a)[0]), "r"((a)[1]), "r"((a)[2]), "r"((a)[3]), \
                   "r"(b0v), "r"(b1v))

// pack two f32 -> f16x2 (lo = s0, hi = s1)
__device__ __forceinline__ __half2 packh2(float s0, float s1) {
    uint32_t p;
    asm("cvt.rn.f16x2.f32 %0, %1, %2;" : "=r"(p) : "f"(s1), "f"(s0));
    return *reinterpret_cast<__half2*>(&p);
}
__device__ __forceinline__ __half2 ex2h2(__half2 a) {
    uint32_t av = *reinterpret_cast<uint32_t*>(&a), ev;
    asm("ex2.approx.f16x2 %0, %1;" : "=r"(ev) : "r"(av));
    return *reinterpret_cast<__half2*>(&ev);
}

// ---------------------------------------------------------------------------
// Kernel 1: row L2-normalize -> fp16 (warp per row), zero rowsum
// ---------------------------------------------------------------------------
__global__ void norm_kernel(const float* __restrict__ feats) {
    int row  = blockIdx.x * 8 + (threadIdx.x >> 5);
    int lane = threadIdx.x & 31;
    float4 v = ((const float4*)(feats + (size_t)row * DD))[lane];
    float ss = v.x * v.x + v.y * v.y + v.z * v.z + v.w * v.w;
    #pragma unroll
    for (int o = 16; o; o >>= 1) ss += __shfl_xor_sync(0xffffffffu, ss, o);
    float inv = 1.0f / fmaxf(sqrtf(ss), 1e-8f);
    __half2 p0 = __floats2half2_rn(v.x * inv, v.y * inv);
    __half2 p1 = __floats2half2_rn(v.z * inv, v.w * inv);
    uint2 pk;
    pk.x = *(uint32_t*)&p0;
    pk.y = *(uint32_t*)&p1;
    *(uint2*)(g_h + (size_t)row * 64 + lane * 2) = pk;
    if (lane == 0) g_rowsum[row] = 0.0f;
}

// ---------------------------------------------------------------------------
// Kernel 2: triangular pair sweep, barrier-free (R15) + fp16x2 clean epilogue
// ---------------------------------------------------------------------------
__device__ __forceinline__ void copy_tile_async(uint32_t smemBase,
                                                const uint4* __restrict__ src,
                                                int tid) {
    #pragma unroll
    for (int i = 0; i < 8; i++) {
        int idx = tid + i * 256;
        int r = idx >> 4, c = idx & 15;
        uint32_t dst = smemBase + (uint32_t)((r * 16 + (c ^ (r & 7))) << 4);
        cp16(dst, src + idx);
    }
}

__global__ void __launch_bounds__(256, 2) sim_kernel() {
    extern __shared__ uint4 sm4[];
    const int tid  = threadIdx.x;
    const int lane = tid & 31;
    const int wid  = tid >> 5;

    // decode bid -> (rt, pairIdx); pairs(rt) = 32 - (rt>>1)
    int rt = 0, cum = 0;
    {
        const int bid = blockIdx.x;
        while (cum + (32 - (rt >> 1)) <= bid) { cum += 32 - (rt >> 1); rt++; }
    }
    const int pairIdx = (int)blockIdx.x - cum;
    const int ct0  = rt + 2 * pairIdx;
    const int numT = (ct0 + 1 < NTILE) ? 2 : 1;
    const int rowBase = rt * 128;

    const uint32_t smA  = smem_u32(sm4);
    const uint32_t smB0 = smA + 32768;
    const uint32_t smB1 = smA + 65536;

    // prologue: load A, B0, B1; single wait + barrier; barrier-free after
    copy_tile_async(smA, (const uint4*)g_h + (size_t)rowBase * 16, tid);
    if (ct0 != rt)
        copy_tile_async(smB0, (const uint4*)g_h + (size_t)(ct0 * 128) * 16, tid);
    if (numT == 2)
        copy_tile_async(smB1, (const uint4*)g_h + (size_t)((ct0 + 1) * 128) * 16, tid);
    CP_COMMIT();
    CP_WAIT(0);
    __syncthreads();

    const int warpM = wid & 1;
    const int warpN = wid >> 1;
    const int aRowL = warpM * 64 + (lane & 15);
    const int aCB   = lane >> 4;
    const int bRowL = warpN * 32 + ((lane & 7) | ((lane >> 1) & 8));
    const int bCB   = (lane >> 3) & 1;

    const int rBase0 = rowBase + warpM * 64 + (lane >> 2);
    const int cOffW  = warpN * 32 + (lane & 3) * 2;

    const __half2 k2c2 = __floats2half2_rn(K2C, K2C);
    const __half2 csh2 = __floats2half2_rn(CSH, CSH);

    float racc[4][2];
    #pragma unroll
    for (int u = 0; u < 4; u++) { racc[u][0] = 0.0f; racc[u][1] = 0.0f; }

    for (int t = 0; t < numT; t++) {
        const int ct = ct0 + t;
        const int colBase = ct * 128;
        const bool isDiag = (ct == rt);
        const bool hasPos = (ct == rt + 32);
        const uint32_t smB = isDiag ? smA : (t == 0 ? smB0 : smB1);

        float C[4][4][4];
        #pragma unroll
        for (int mi = 0; mi < 4; mi++)
            #pragma unroll
            for (int nj = 0; nj < 4; nj++)
                #pragma unroll
                for (int q = 0; q < 4; q++) C[mi][nj][q] = 0.0f;

        #pragma unroll
        for (int ks = 0; ks < 8; ks++) {
            uint32_t a[4][4], b[2][4];
            #pragma unroll
            for (int mi = 0; mi < 4; mi++) {
                int r = aRowL + mi * 16;
                int ch = 2 * ks + aCB;
                LDSM4(a[mi][0], a[mi][1], a[mi][2], a[mi][3],
                      smA + r * 256 + ((ch ^ (r & 7)) << 4));
            }
            #pragma unroll
            for (int nh = 0; nh < 2; nh++) {
                int r = bRowL + nh * 16;
                int ch = 2 * ks + bCB;
                LDSM4(b[nh][0], b[nh][1], b[nh][2], b[nh][3],
                      smB + r * 256 + ((ch ^ (r & 7)) << 4));
            }
            #pragma unroll
            for (int mi = 0; mi < 4; mi++)
                #pragma unroll
                for (int nj = 0; nj < 4; nj++)
                    MMA16816(C[mi][nj], a[mi], b[nj >> 1][(nj & 1) * 2],
                             b[nj >> 1][(nj & 1) * 2 + 1]);
        }

        // ---- epilogues (no barriers); all use the 2^SSH shift ----
        const int cBase0 = colBase + cOffW;
        if (isDiag) {
            // 64 tiles: row-only, diag-skip compare (fp32)
            #pragma unroll
            for (int mi = 0; mi < 4; mi++)
                #pragma unroll
                for (int h = 0; h < 2; h++) {
                    const int grow = rBase0 + mi * 16 + h * 8;
                    float acc = 0.0f;
                    #pragma unroll
                    for (int nj = 0; nj < 4; nj++)
                        #pragma unroll
                        for (int q = 0; q < 2; q++) {
                            const int gcol = cBase0 + nj * 8 + q;
                            const float s = C[mi][nj][h * 2 + q];
                            if (gcol != grow) acc += ex2f(fmaf(s, K2C, CSH));
                        }
                    racc[mi][h] += acc;
                }
        } else if (hasPos) {
            // 32 tiles: fp32 dual-acc + pos capture
            float cacc[4][2];
            #pragma unroll
            for (int u = 0; u < 4; u++) { cacc[u][0] = 0.0f; cacc[u][1] = 0.0f; }
            #pragma unroll
            for (int mi = 0; mi < 4; mi++)
                #pragma unroll
                for (int h = 0; h < 2; h++) {
                    const int grow = rBase0 + mi * 16 + h * 8;
                    const int pcol = grow ^ (NN / 2);
                    float acc = 0.0f;
                    #pragma unroll
                    for (int nj = 0; nj < 4; nj++)
                        #pragma unroll
                        for (int q = 0; q < 2; q++) {
                            const int gcol = cBase0 + nj * 8 + q;
                            const float s = C[mi][nj][h * 2 + q];
                            const float e = ex2f(fmaf(s, K2C, CSH));
                            acc += e;
                            cacc[nj][q] += e;
                            if (gcol == pcol) {
                                g_pos[grow] = s;
                                g_pos[gcol] = s;
                            }
                        }
                    racc[mi][h] += acc;
                }
            #pragma unroll
            for (int nj = 0; nj < 4; nj++)
                #pragma unroll
                for (int q = 0; q < 2; q++) {
                    float v = cacc[nj][q];
                    v += __shfl_xor_sync(0xffffffffu, v, 4);
                    v += __shfl_xor_sync(0xffffffffu, v, 8);
                    v += __shfl_xor_sync(0xffffffffu, v, 16);
                    if (lane < 4)
                        atomicAdd(&g_rowsum[cBase0 + nj * 8 + q], v);
                }
        } else {
            // 1984 tiles: fp16x2 clean path — 2 elements per instruction
            __half2 cacc2[4];
            #pragma unroll
            for (int u = 0; u < 4; u++) cacc2[u] = __float2half2_rn(0.0f);
            #pragma unroll
            for (int mi = 0; mi < 4; mi++)
                #pragma unroll
                for (int h = 0; h < 2; h++) {
                    __half2 acc2 = __float2half2_rn(0.0f);
                    #pragma unroll
                    for (int nj = 0; nj < 4; nj++) {
                        __half2 sp = packh2(C[mi][nj][h * 2 + 0],
                                            C[mi][nj][h * 2 + 1]);
                        __half2 e2 = ex2h2(__hfma2(sp, k2c2, csh2));
                        acc2 = __hadd2(acc2, e2);
                        cacc2[nj] = __hadd2(cacc2[nj], e2);
                    }
                    racc[mi][h] += __low2float(acc2) + __high2float(acc2);
                }
            // column flush in h2 (halves = q0,q1)
            #pragma unroll
            for (int nj = 0; nj < 4; nj++) {
                __half2 v2 = cacc2[nj];
                #pragma unroll
                for (int o = 4; o <= 16; o <<= 1) {
                    uint32_t u = __shfl_xor_sync(0xffffffffu,
                                                 *reinterpret_cast<uint32_t*>(&v2), o);
                    v2 = __hadd2(v2, *reinterpret_cast<__half2*>(&u));
                }
                if (lane < 4) {
                    atomicAdd(&g_rowsum[cBase0 + nj * 8 + 0], __low2float(v2));
                    atomicAdd(&g_rowsum[cBase0 + nj * 8 + 1], __high2float(v2));
                }
            }
        }
    }

    // row reduction once for both tiles
    #pragma unroll
    for (int mi = 0; mi < 4; mi++)
        #pragma unroll
        for (int h = 0; h < 2; h++) {
            float v = racc[mi][h];
            v += __shfl_xor_sync(0xffffffffu, v, 1);
            v += __shfl_xor_sync(0xffffffffu, v, 2);
            if ((lane & 3) == 0)
                atomicAdd(&g_rowsum[rBase0 + mi * 16 + h * 8], v);
        }
}

// ---------------------------------------------------------------------------
// Kernel 3: loss = mean( (1 - pos)/T + ln(rowsum) - SSH*ln2 )
// ---------------------------------------------------------------------------
__global__ void finish_kernel(float* __restrict__ out) {
    __shared__ float red[1024];
    const int tid = threadIdx.x;
    float acc = 0.0f;
    for (int r = tid; r < NN; r += 1024)
        acc += (1.0f - g_pos[r]) * (1.0f / 0.07f)
             + (lg2f(g_rowsum[r]) - SSH) * 0.69314718f;
    red[tid] = acc;
    __syncthreads();
    #pragma unroll
    for (int s = 512; s > 0; s >>= 1) {
        if (tid < s) red[tid] += red[tid + s];
        __syncthreads();
    }
    if (tid == 0) out[0] = red[0] / (float)NN;
}

// ---------------------------------------------------------------------------
extern "C" void kernel_launch(void* const* d_in, const int* in_sizes, int n_in,
                              void* d_out, int out_size) {
    const float* feats = (const float*)d_in[0];
    float* out = (float*)d_out;

    cudaFuncSetAttribute(sim_kernel, cudaFuncAttributeMaxDynamicSharedMemorySize,
                         SMEM_BYTES);

    norm_kernel<<<NN / 8, 256>>>(feats);
    sim_kernel<<<NPAIR, 256, SMEM_BYTES>>>();
    finish_kernel<<<1, 1024>>>(out);
}